// round 10
// baseline (speedup 1.0000x reference)
#include <cuda_runtime.h>
#include <cuda_bf16.h>

#define BD 512
#define DD 512
#define NL 3
#define NK 100
#define NTHREADS 256
#define BETA 98.999992f

// One block per batch row; h lives in smem across all 3 layers.
// Linear-phi fast paths:
//  (a) HISTOGRAM (lin && all h>=0): one-clamp threshold ou=ceil((1-h)/eta) is
//      an integer bin; prefix sums of (lam, lam*h) over 512 bins give
//      satsum(o) in O(1) per output. Exact. Used by layer 0.
//  (b) COMPACTION (lin): dense (h,lam) list of non-saturated elements,
//      2-inst/eval loop. Used by layers 1-2 (few survivors).
//  (c) TABLE fallback (non-linear phi): lane-replicated gather. Exact.
__global__ __launch_bounds__(NTHREADS) void sprecher_kernel(
    const float* __restrict__ x,
    const float* __restrict__ lambdas,
    const float* __restrict__ eta,
    const float* __restrict__ phi_log_inc,
    const float* __restrict__ Phi_coeffs,
    const float* __restrict__ dc_p, const float* __restrict__ dr_p,
    const float* __restrict__ cc_p, const float* __restrict__ cr_p,
    const float* __restrict__ res_w,
    const float* __restrict__ output_scale,
    float* __restrict__ out)
{
    __shared__ float  h[DD];
    __shared__ __align__(16) float2 phi_tab[99 * 32]; // table / compact list / hist bins
    __shared__ float4 hl4[DD / 2];                    // fallback broadcast quads
    __shared__ float  Phic[NK];
    __shared__ float  coef[NK];
    __shared__ float  s_cmin, s_cmax, s_inv, s_gamma, s_Tl, s_Tlh, s_S1, s_hmin;
    __shared__ int    s_nact;
    __shared__ float  rA[8], rB[8], rC[8], rD[8], rE[8], rF[8], rG[8];
    __shared__ float2 wsum2[8];
    __shared__ int    wcnt[8];

    const int b    = blockIdx.x;
    const int tid  = threadIdx.x;
    const int lane = tid & 31;
    const int wid  = tid >> 5;

    for (int i = tid; i < DD; i += NTHREADS) h[i] = x[b * DD + i];

    const float dcv = dc_p[0], drv = dr_p[0], ccv = cc_p[0], crv = cr_p[0];
    const float in_min = dcv - drv, in_max = dcv + drv;
    const float o_min  = ccv - crv, o_max  = ccv + crv;
    const float cap_scale = 99.0f / (in_max - in_min);
    const float2* __restrict__ tabL = (const float2*)phi_tab + lane;

    for (int l = 0; l < NL; ++l) {
        const float etal = eta[l];
        const float rw   = res_w[l];

        __syncthreads();                                   // B0: h ready, prev smem reads done

        float sp = 0.f, pc = 0.f;
        if (tid < NK) {
            float v = phi_log_inc[l * NK + tid];
            sp = (v > 20.f) ? v : log1pf(expf(v));         // softplus
            coef[tid] = sp;
            pc = Phi_coeffs[l * NK + tid];
            Phic[tid] = pc;
        }

        // this thread's two elements (2*tid, 2*tid+1)
        const float2 lm = ((const float2*)(lambdas + l * DD))[tid];
        const float hx = h[2 * tid], hz = h[2 * tid + 1];

        // block reductions: Tl, Tlh, S1 (lam where h>=1), hmin, Phic min/max, sum softplus
        float tl  = lm.x + lm.y;
        float tlh = lm.x * hx + lm.y * hz;
        float s1  = ((hx >= 1.0f) ? lm.x : 0.f) + ((hz >= 1.0f) ? lm.y : 0.f);
        float hmn = fminf(hx, hz);
        float mn  = (tid < NK) ? pc : 3.0e38f;
        float mx  = (tid < NK) ? pc : -3.0e38f;
        float ss  = sp;
        #pragma unroll
        for (int off = 16; off > 0; off >>= 1) {
            tl  += __shfl_xor_sync(~0u, tl,  off);
            tlh += __shfl_xor_sync(~0u, tlh, off);
            s1  += __shfl_xor_sync(~0u, s1,  off);
            hmn  = fminf(hmn, __shfl_xor_sync(~0u, hmn, off));
            mn   = fminf(mn,  __shfl_xor_sync(~0u, mn,  off));
            mx   = fmaxf(mx,  __shfl_xor_sync(~0u, mx,  off));
            ss  += __shfl_xor_sync(~0u, ss, off);
        }
        if (lane == 0) { rA[wid]=tl; rB[wid]=tlh; rC[wid]=s1; rD[wid]=hmn;
                         rE[wid]=mn; rF[wid]=mx; rG[wid]=ss; }
        __syncthreads();                                   // B1
        if (tid == 0) {
            float Tl=0.f, Tlh=0.f, S1=0.f, Hm=3.0e38f, Mn=3.0e38f, Mx=-3.0e38f, Ss=0.f;
            #pragma unroll
            for (int w = 0; w < 8; ++w) {
                Tl += rA[w]; Tlh += rB[w]; S1 += rC[w];
                Hm = fminf(Hm, rD[w]);
                Mn = fminf(Mn, rE[w]); Mx = fmaxf(Mx, rF[w]); Ss += rG[w];
            }
            s_Tl = Tl; s_Tlh = Tlh; s_S1 = S1; s_hmin = Hm;
            s_cmin = Mn; s_cmax = Mx;
            s_gamma = coef[0] / (Ss + 1e-8f);
        }
        // zero histogram bins (harmless for other paths; overwritten there)
        const float2 z2 = make_float2(0.f, 0.f);
        phi_tab[tid] = z2; phi_tab[tid + NTHREADS] = z2;

        const float coef0 = coef[0];                       // visible after B1
        const int lin = __syncthreads_and(tid >= NK ||
                           fabsf(sp - coef0) <= 1e-6f * fabsf(coef0));  // B2

        const float co0 = etal * (float)tid;
        const float co1 = etal * (float)(tid + NTHREADS);
        float acc0 = 0.f, acc1 = 0.f;

        if (lin && s_hmin >= 0.f) {
            // ---- HISTOGRAM path (all h >= 0, only upper clamp) ----
            const float inv_eta = 1.0f / etal;
            {
                int ou = __float2int_ru((1.0f - hx) * inv_eta);
                ou = max(ou, 0);
                if (ou <= 511) { atomicAdd(&phi_tab[ou].x, lm.x);
                                 atomicAdd(&phi_tab[ou].y, lm.x * hx); }
                int ov = __float2int_ru((1.0f - hz) * inv_eta);
                ov = max(ov, 0);
                if (ov <= 511) { atomicAdd(&phi_tab[ov].x, lm.y);
                                 atomicAdd(&phi_tab[ov].y, lm.y * hz); }
            }
            __syncthreads();                               // B3: hist complete
            // inclusive float2 scan over 512 bins (2 bins/thread)
            float4 ac = ((const float4*)phi_tab)[tid];
            float2 s = make_float2(ac.x + ac.z, ac.y + ac.w);
            #pragma unroll
            for (int d = 1; d < 32; d <<= 1) {
                float nx = __shfl_up_sync(~0u, s.x, d);
                float ny = __shfl_up_sync(~0u, s.y, d);
                if (lane >= d) { s.x += nx; s.y += ny; }
            }
            if (lane == 31) wsum2[wid] = s;
            __syncthreads();                               // B4
            float ox = 0.f, oy = 0.f;
            #pragma unroll
            for (int w = 0; w < 8; ++w)
                if (w < wid) { ox += wsum2[w].x; oy += wsum2[w].y; }
            float p1x = ox + s.x, p1y = oy + s.y;
            ((float4*)phi_tab)[tid] = make_float4(p1x - ac.z, p1y - ac.w, p1x, p1y);
            __syncthreads();                               // B5
            const float Tl = s_Tl, Tlh = s_Tlh;
            const float g99  = 99.0f * s_gamma;
            const float base = s_gamma * Tl;
            {
                float2 P = phi_tab[tid];
                float satsum = P.x + (Tlh - P.y) + co0 * (Tl - P.x);
                acc0 = fmaf(g99, satsum, base);
            }
            {
                float2 P = phi_tab[tid + NTHREADS];
                float satsum = P.x + (Tlh - P.y) + co1 * (Tl - P.x);
                acc1 = fmaf(g99, satsum, base);
            }
        } else if (lin) {
            // ---- COMPACTION path ----
            const float comax = etal * 511.0f;
            const bool a0 = (hx > -comax) && (hx < 1.0f);
            const bool a1 = (hz > -comax) && (hz < 1.0f);
            int c = (int)a0 + (int)a1;
            int incl = c;
            #pragma unroll
            for (int d = 1; d < 32; d <<= 1) {
                int n = __shfl_up_sync(~0u, incl, d);
                if (lane >= d) incl += n;
            }
            if (lane == 31) wcnt[wid] = incl;
            __syncthreads();                               // B3
            int wbase = 0;
            #pragma unroll
            for (int w = 0; w < 8; ++w) if (w < wid) wbase += wcnt[w];
            int pos = wbase + incl - c;
            if (a0) phi_tab[pos++] = make_float2(hx, lm.x);
            if (a1) phi_tab[pos]   = make_float2(hz, lm.y);
            if (tid == 0) {
                int tot = 0;
                #pragma unroll
                for (int w = 0; w < 8; ++w) tot += wcnt[w];
                if (tot & 1) { phi_tab[tot] = make_float2(0.f, 0.f); tot++; }
                s_nact = tot;
            }
            __syncthreads();                               // B4
            const int n2 = s_nact >> 1;
            const float4* __restrict__ lst = (const float4*)phi_tab;
            #pragma unroll 4
            for (int j = 0; j < n2; ++j) {
                const float4 hv = lst[j];
                acc0 = fmaf(hv.y, __saturatef(hv.x + co0), acc0);
                acc1 = fmaf(hv.y, __saturatef(hv.x + co1), acc1);
                acc0 = fmaf(hv.w, __saturatef(hv.z + co0), acc0);
                acc1 = fmaf(hv.w, __saturatef(hv.z + co1), acc1);
            }
            const float g99  = 99.0f * s_gamma;
            const float base = s_gamma * s_Tl;
            const float S1v  = s_S1;
            acc0 = fmaf(g99, acc0 + S1v, base);
            acc1 = fmaf(g99, acc1 + S1v, base);
        } else {
            // ---- TABLE fallback (exact piecewise-linear phi) ----
            if (tid == 0) {
                float cum = 0.f;
                for (int k = 0; k < NK; ++k) { cum += coef[k]; coef[k] = cum; }
                s_inv = 1.0f / (cum + 1e-8f);
            }
            hl4[tid] = make_float4(hx, lm.x, hz, lm.y);
            __syncthreads();
            {
                const float inv = s_inv;
                const float fix = 99.0f / BETA;
                for (int idx = tid; idx < 99 * 32; idx += NTHREADS) {
                    int k = idx >> 5;
                    float c0 = coef[k] * inv;
                    float dk = coef[k + 1] * inv - c0;
                    phi_tab[idx] = make_float2(dk * fix, fmaf(-(float)k, dk, c0));
                }
            }
            __syncthreads();
            #pragma unroll 4
            for (int i2 = 0; i2 < DD / 2; ++i2) {
                const float4 hv = hl4[i2];
                { float u = __saturatef(hv.x + co0) * BETA; float2 t = tabL[((int)u) * 32];
                  acc0 = fmaf(hv.y, fmaf(u, t.x, t.y), acc0); }
                { float u = __saturatef(hv.x + co1) * BETA; float2 t = tabL[((int)u) * 32];
                  acc1 = fmaf(hv.y, fmaf(u, t.x, t.y), acc1); }
                { float u = __saturatef(hv.z + co0) * BETA; float2 t = tabL[((int)u) * 32];
                  acc0 = fmaf(hv.w, fmaf(u, t.x, t.y), acc0); }
                { float u = __saturatef(hv.z + co1) * BETA; float2 t = tabL[((int)u) * 32];
                  acc1 = fmaf(hv.w, fmaf(u, t.x, t.y), acc1); }
            }
        }

        // Epilogue: Phi spline + renorm + residual
        const float cmin = s_cmin, cmax = s_cmax;
        const float inv_norm = 1.0f / (cmax - cmin + 1e-8f);
        float act0, act1;
        {
            float s   = acc0 + (float)tid;
            float scv = fminf(fmaxf(s, in_min), in_max);
            float u   = (scv - in_min) * cap_scale;
            int   k   = (int)u; k = min(k, 98);
            float f   = u - (float)k;
            float c0  = Phic[k], c1 = Phic[k + 1];
            float raw = fmaf(f, c1 - c0, c0);
            float rn  = fminf(fmaxf((raw - cmin) * inv_norm, 0.f), 1.f);
            act0 = fmaf(o_max - o_min, rn, o_min) + rw * h[tid];
        }
        {
            float s   = acc1 + (float)(tid + NTHREADS);
            float scv = fminf(fmaxf(s, in_min), in_max);
            float u   = (scv - in_min) * cap_scale;
            int   k   = (int)u; k = min(k, 98);
            float f   = u - (float)k;
            float c0  = Phic[k], c1 = Phic[k + 1];
            float raw = fmaf(f, c1 - c0, c0);
            float rn  = fminf(fmaxf((raw - cmin) * inv_norm, 0.f), 1.f);
            act1 = fmaf(o_max - o_min, rn, o_min) + rw * h[tid + NTHREADS];
        }

        if (l < NL - 1) {
            __syncthreads();
            h[tid]            = act0;
            h[tid + NTHREADS] = act1;
        } else {
            float v = act0 + act1;
            #pragma unroll
            for (int off = 16; off > 0; off >>= 1)
                v += __shfl_xor_sync(0xffffffffu, v, off);
            if (lane == 0) rA[wid] = v;
            __syncthreads();
            if (tid == 0) {
                float r = 0.f;
                #pragma unroll
                for (int w = 0; w < NTHREADS / 32; ++w) r += rA[w];
                out[b] = r * output_scale[0];
            }
        }
    }
}

extern "C" void kernel_launch(void* const* d_in, const int* in_sizes, int n_in,
                              void* d_out, int out_size)
{
    const float* x            = (const float*)d_in[0];
    const float* lambdas      = (const float*)d_in[1];
    const float* eta          = (const float*)d_in[2];
    const float* phi_log_inc  = (const float*)d_in[3];
    const float* Phi_coeffs   = (const float*)d_in[4];
    const float* dc           = (const float*)d_in[5];
    const float* dr           = (const float*)d_in[6];
    const float* cc           = (const float*)d_in[7];
    const float* cr           = (const float*)d_in[8];
    const float* res_w        = (const float*)d_in[9];
    const float* output_scale = (const float*)d_in[10];
    float* out = (float*)d_out;

    sprecher_kernel<<<BD, NTHREADS>>>(x, lambdas, eta, phi_log_inc, Phi_coeffs,
                                      dc, dr, cc, cr, res_w, output_scale, out);
}

// round 12
// speedup vs baseline: 3.0403x; 3.0403x over previous
#include <cuda_runtime.h>
#include <cuda_bf16.h>

#define BD 512
#define DD 512
#define NL 3
#define NK 100
#define NTHREADS 256
#define BETA 98.999992f

// One block per batch row; h lives in smem across all 3 layers.
// Linear-phi fast paths:
//  (a) HISTOGRAM: only when lin && 0 <= h < 1 for ALL elements (layer-0
//      regime: no element permanently saturated, thresholds spread across
//      bins so smem atomics don't serialize). ou=ceil((1-h)/eta) bins +
//      prefix sums of (lam, lam*h) give satsum(o) in O(1)/output. Exact.
//  (b) COMPACTION: lin, some elements saturated -> dense (h,lam) list of
//      survivors, 2-inst/eval loop. Layers 1-2 take this (few survivors).
//  (c) TABLE fallback (non-linear phi): lane-replicated gather. Exact.
__global__ __launch_bounds__(NTHREADS) void sprecher_kernel(
    const float* __restrict__ x,
    const float* __restrict__ lambdas,
    const float* __restrict__ eta,
    const float* __restrict__ phi_log_inc,
    const float* __restrict__ Phi_coeffs,
    const float* __restrict__ dc_p, const float* __restrict__ dr_p,
    const float* __restrict__ cc_p, const float* __restrict__ cr_p,
    const float* __restrict__ res_w,
    const float* __restrict__ output_scale,
    float* __restrict__ out)
{
    __shared__ float  h[DD];
    __shared__ __align__(16) float2 phi_tab[99 * 32]; // table / compact list / hist bins
    __shared__ float4 hl4[DD / 2];                    // fallback broadcast quads
    __shared__ float  Phic[NK];
    __shared__ float  coef[NK];
    __shared__ float  s_cmin, s_cmax, s_inv, s_gamma, s_Tl, s_Tlh, s_S1, s_hmin, s_hmax;
    __shared__ int    s_nact;
    __shared__ float  rA[8], rB[8], rC[8], rD[8], rE[8], rF[8], rG[8], rH[8];
    __shared__ float2 wsum2[8];
    __shared__ int    wcnt[8];

    const int b    = blockIdx.x;
    const int tid  = threadIdx.x;
    const int lane = tid & 31;
    const int wid  = tid >> 5;

    for (int i = tid; i < DD; i += NTHREADS) h[i] = x[b * DD + i];

    const float dcv = dc_p[0], drv = dr_p[0], ccv = cc_p[0], crv = cr_p[0];
    const float in_min = dcv - drv, in_max = dcv + drv;
    const float o_min  = ccv - crv, o_max  = ccv + crv;
    const float cap_scale = 99.0f / (in_max - in_min);
    const float2* __restrict__ tabL = (const float2*)phi_tab + lane;

    for (int l = 0; l < NL; ++l) {
        const float etal = eta[l];
        const float rw   = res_w[l];

        __syncthreads();                                   // B0: h ready, prev smem reads done

        float sp = 0.f, pc = 0.f;
        if (tid < NK) {
            float v = phi_log_inc[l * NK + tid];
            sp = (v > 20.f) ? v : log1pf(expf(v));         // softplus
            coef[tid] = sp;
            pc = Phi_coeffs[l * NK + tid];
            Phic[tid] = pc;
        }

        // this thread's two elements (2*tid, 2*tid+1)
        const float2 lm = ((const float2*)(lambdas + l * DD))[tid];
        const float hx = h[2 * tid], hz = h[2 * tid + 1];

        // block reductions
        float tl  = lm.x + lm.y;
        float tlh = lm.x * hx + lm.y * hz;
        float s1  = ((hx >= 1.0f) ? lm.x : 0.f) + ((hz >= 1.0f) ? lm.y : 0.f);
        float hmn = fminf(hx, hz);
        float hmx = fmaxf(hx, hz);
        float mn  = (tid < NK) ? pc : 3.0e38f;
        float mx  = (tid < NK) ? pc : -3.0e38f;
        float ss  = sp;
        #pragma unroll
        for (int off = 16; off > 0; off >>= 1) {
            tl  += __shfl_xor_sync(~0u, tl,  off);
            tlh += __shfl_xor_sync(~0u, tlh, off);
            s1  += __shfl_xor_sync(~0u, s1,  off);
            hmn  = fminf(hmn, __shfl_xor_sync(~0u, hmn, off));
            hmx  = fmaxf(hmx, __shfl_xor_sync(~0u, hmx, off));
            mn   = fminf(mn,  __shfl_xor_sync(~0u, mn,  off));
            mx   = fmaxf(mx,  __shfl_xor_sync(~0u, mx,  off));
            ss  += __shfl_xor_sync(~0u, ss, off);
        }
        if (lane == 0) { rA[wid]=tl; rB[wid]=tlh; rC[wid]=s1; rD[wid]=hmn;
                         rE[wid]=mn; rF[wid]=mx; rG[wid]=ss; rH[wid]=hmx; }
        __syncthreads();                                   // B1
        if (tid == 0) {
            float Tl=0.f, Tlh=0.f, S1=0.f, Hm=3.0e38f, Hx=-3.0e38f,
                  Mn=3.0e38f, Mx=-3.0e38f, Ss=0.f;
            #pragma unroll
            for (int w = 0; w < 8; ++w) {
                Tl += rA[w]; Tlh += rB[w]; S1 += rC[w];
                Hm = fminf(Hm, rD[w]); Hx = fmaxf(Hx, rH[w]);
                Mn = fminf(Mn, rE[w]); Mx = fmaxf(Mx, rF[w]); Ss += rG[w];
            }
            s_Tl = Tl; s_Tlh = Tlh; s_S1 = S1; s_hmin = Hm; s_hmax = Hx;
            s_cmin = Mn; s_cmax = Mx;
            s_gamma = coef[0] / (Ss + 1e-8f);
        }
        // zero histogram bins (only the hist path reads them as bins)
        const float2 z2 = make_float2(0.f, 0.f);
        phi_tab[tid] = z2; phi_tab[tid + NTHREADS] = z2;

        const float coef0 = coef[0];                       // visible after B1
        const int lin = __syncthreads_and(tid >= NK ||
                           fabsf(sp - coef0) <= 1e-6f * fabsf(coef0));  // B2

        const float co0 = etal * (float)tid;
        const float co1 = etal * (float)(tid + NTHREADS);
        float acc0 = 0.f, acc1 = 0.f;

        if (lin && s_hmin >= 0.f && s_hmax < 1.0f) {
            // ---- HISTOGRAM path: all h in [0,1), thresholds spread ----
            const float inv_eta = 1.0f / etal;
            {
                int ou = __float2int_ru((1.0f - hx) * inv_eta);
                ou = max(ou, 0);
                if (ou <= 511) { atomicAdd(&phi_tab[ou].x, lm.x);
                                 atomicAdd(&phi_tab[ou].y, lm.x * hx); }
                int ov = __float2int_ru((1.0f - hz) * inv_eta);
                ov = max(ov, 0);
                if (ov <= 511) { atomicAdd(&phi_tab[ov].x, lm.y);
                                 atomicAdd(&phi_tab[ov].y, lm.y * hz); }
            }
            __syncthreads();                               // B3: hist complete
            // inclusive float2 scan over 512 bins (2 bins/thread)
            float4 ac = ((const float4*)phi_tab)[tid];
            float2 s = make_float2(ac.x + ac.z, ac.y + ac.w);
            #pragma unroll
            for (int d = 1; d < 32; d <<= 1) {
                float nx = __shfl_up_sync(~0u, s.x, d);
                float ny = __shfl_up_sync(~0u, s.y, d);
                if (lane >= d) { s.x += nx; s.y += ny; }
            }
            if (lane == 31) wsum2[wid] = s;
            __syncthreads();                               // B4
            float ox = 0.f, oy = 0.f;
            #pragma unroll
            for (int w = 0; w < 8; ++w)
                if (w < wid) { ox += wsum2[w].x; oy += wsum2[w].y; }
            float p1x = ox + s.x, p1y = oy + s.y;
            ((float4*)phi_tab)[tid] = make_float4(p1x - ac.z, p1y - ac.w, p1x, p1y);
            __syncthreads();                               // B5
            const float Tl = s_Tl, Tlh = s_Tlh;
            const float g99  = 99.0f * s_gamma;
            const float base = s_gamma * Tl;
            {
                float2 P = phi_tab[tid];
                float satsum = P.x + (Tlh - P.y) + co0 * (Tl - P.x);
                acc0 = fmaf(g99, satsum, base);
            }
            {
                float2 P = phi_tab[tid + NTHREADS];
                float satsum = P.x + (Tlh - P.y) + co1 * (Tl - P.x);
                acc1 = fmaf(g99, satsum, base);
            }
        } else if (lin) {
            // ---- COMPACTION path (some elements permanently clamped) ----
            const float comax = etal * 511.0f;
            const bool a0 = (hx > -comax) && (hx < 1.0f);
            const bool a1 = (hz > -comax) && (hz < 1.0f);
            int c = (int)a0 + (int)a1;
            int incl = c;
            #pragma unroll
            for (int d = 1; d < 32; d <<= 1) {
                int n = __shfl_up_sync(~0u, incl, d);
                if (lane >= d) incl += n;
            }
            if (lane == 31) wcnt[wid] = incl;
            __syncthreads();                               // B3
            int wbase = 0;
            #pragma unroll
            for (int w = 0; w < 8; ++w) if (w < wid) wbase += wcnt[w];
            int pos = wbase + incl - c;
            if (a0) phi_tab[pos++] = make_float2(hx, lm.x);
            if (a1) phi_tab[pos]   = make_float2(hz, lm.y);
            if (tid == 0) {
                int tot = 0;
                #pragma unroll
                for (int w = 0; w < 8; ++w) tot += wcnt[w];
                if (tot & 1) { phi_tab[tot] = make_float2(0.f, 0.f); tot++; }
                s_nact = tot;
            }
            __syncthreads();                               // B4
            const int n2 = s_nact >> 1;
            const float4* __restrict__ lst = (const float4*)phi_tab;
            #pragma unroll 4
            for (int j = 0; j < n2; ++j) {
                const float4 hv = lst[j];
                acc0 = fmaf(hv.y, __saturatef(hv.x + co0), acc0);
                acc1 = fmaf(hv.y, __saturatef(hv.x + co1), acc1);
                acc0 = fmaf(hv.w, __saturatef(hv.z + co0), acc0);
                acc1 = fmaf(hv.w, __saturatef(hv.z + co1), acc1);
            }
            const float g99  = 99.0f * s_gamma;
            const float base = s_gamma * s_Tl;
            const float S1v  = s_S1;
            acc0 = fmaf(g99, acc0 + S1v, base);
            acc1 = fmaf(g99, acc1 + S1v, base);
        } else {
            // ---- TABLE fallback (exact piecewise-linear phi) ----
            if (tid == 0) {
                float cum = 0.f;
                for (int k = 0; k < NK; ++k) { cum += coef[k]; coef[k] = cum; }
                s_inv = 1.0f / (cum + 1e-8f);
            }
            hl4[tid] = make_float4(hx, lm.x, hz, lm.y);
            __syncthreads();
            {
                const float inv = s_inv;
                const float fix = 99.0f / BETA;
                for (int idx = tid; idx < 99 * 32; idx += NTHREADS) {
                    int k = idx >> 5;
                    float c0 = coef[k] * inv;
                    float dk = coef[k + 1] * inv - c0;
                    phi_tab[idx] = make_float2(dk * fix, fmaf(-(float)k, dk, c0));
                }
            }
            __syncthreads();
            #pragma unroll 4
            for (int i2 = 0; i2 < DD / 2; ++i2) {
                const float4 hv = hl4[i2];
                { float u = __saturatef(hv.x + co0) * BETA; float2 t = tabL[((int)u) * 32];
                  acc0 = fmaf(hv.y, fmaf(u, t.x, t.y), acc0); }
                { float u = __saturatef(hv.x + co1) * BETA; float2 t = tabL[((int)u) * 32];
                  acc1 = fmaf(hv.y, fmaf(u, t.x, t.y), acc1); }
                { float u = __saturatef(hv.z + co0) * BETA; float2 t = tabL[((int)u) * 32];
                  acc0 = fmaf(hv.w, fmaf(u, t.x, t.y), acc0); }
                { float u = __saturatef(hv.z + co1) * BETA; float2 t = tabL[((int)u) * 32];
                  acc1 = fmaf(hv.w, fmaf(u, t.x, t.y), acc1); }
            }
        }

        // Epilogue: Phi spline + renorm + residual
        const float cmin = s_cmin, cmax = s_cmax;
        const float inv_norm = 1.0f / (cmax - cmin + 1e-8f);
        float act0, act1;
        {
            float s   = acc0 + (float)tid;
            float scv = fminf(fmaxf(s, in_min), in_max);
            float u   = (scv - in_min) * cap_scale;
            int   k   = (int)u; k = min(k, 98);
            float f   = u - (float)k;
            float c0  = Phic[k], c1 = Phic[k + 1];
            float raw = fmaf(f, c1 - c0, c0);
            float rn  = fminf(fmaxf((raw - cmin) * inv_norm, 0.f), 1.f);
            act0 = fmaf(o_max - o_min, rn, o_min) + rw * h[tid];
        }
        {
            float s   = acc1 + (float)(tid + NTHREADS);
            float scv = fminf(fmaxf(s, in_min), in_max);
            float u   = (scv - in_min) * cap_scale;
            int   k   = (int)u; k = min(k, 98);
            float f   = u - (float)k;
            float c0  = Phic[k], c1 = Phic[k + 1];
            float raw = fmaf(f, c1 - c0, c0);
            float rn  = fminf(fmaxf((raw - cmin) * inv_norm, 0.f), 1.f);
            act1 = fmaf(o_max - o_min, rn, o_min) + rw * h[tid + NTHREADS];
        }

        if (l < NL - 1) {
            __syncthreads();
            h[tid]            = act0;
            h[tid + NTHREADS] = act1;
        } else {
            float v = act0 + act1;
            #pragma unroll
            for (int off = 16; off > 0; off >>= 1)
                v += __shfl_xor_sync(0xffffffffu, v, off);
            if (lane == 0) rA[wid] = v;
            __syncthreads();
            if (tid == 0) {
                float r = 0.f;
                #pragma unroll
                for (int w = 0; w < NTHREADS / 32; ++w) r += rA[w];
                out[b] = r * output_scale[0];
            }
        }
    }
}

extern "C" void kernel_launch(void* const* d_in, const int* in_sizes, int n_in,
                              void* d_out, int out_size)
{
    const float* x            = (const float*)d_in[0];
    const float* lambdas      = (const float*)d_in[1];
    const float* eta          = (const float*)d_in[2];
    const float* phi_log_inc  = (const float*)d_in[3];
    const float* Phi_coeffs   = (const float*)d_in[4];
    const float* dc           = (const float*)d_in[5];
    const float* dr           = (const float*)d_in[6];
    const float* cc           = (const float*)d_in[7];
    const float* cr           = (const float*)d_in[8];
    const float* res_w        = (const float*)d_in[9];
    const float* output_scale = (const float*)d_in[10];
    float* out = (float*)d_out;

    sprecher_kernel<<<BD, NTHREADS>>>(x, lambdas, eta, phi_log_inc, Phi_coeffs,
                                      dc, dr, cc, cr, res_w, output_scale, out);
}

// round 14
// speedup vs baseline: 3.1473x; 1.0352x over previous
#include <cuda_runtime.h>
#include <cuda_bf16.h>

#define BD 512
#define DD 512
#define NL 3
#define NK 100
#define NTHREADS 256
#define BETA 98.999992f

// Layer-constant scratch (written by setup_kernel each launch; deterministic).
struct LayerConst { float lin, gamma, Tl, cmin, cmax; };
__device__ LayerConst g_lc[NL];
__device__ float2     g_tab[NL][NK];   // fallback (A_k, B_k), k < 99

// grid = NL, block = 128: per-layer constants, computed once instead of
// per-block: softplus sum + lin detect, gamma, sum(lambda), Phic min/max,
// and (rare, non-linear phi) the cumulative table.
__global__ __launch_bounds__(128) void setup_kernel(
    const float* __restrict__ lambdas,
    const float* __restrict__ phi_log_inc,
    const float* __restrict__ Phi_coeffs)
{
    const int l = blockIdx.x;
    const int tid = threadIdx.x;
    const int lane = tid & 31, wid = tid >> 5;
    __shared__ float sp[NK];
    __shared__ float cum[NK];
    __shared__ float rS[4], rL[4], rMn[4], rMx[4];
    __shared__ int   rLin[4];

    float v0  = phi_log_inc[l * NK];
    float sp0 = (v0 > 20.f) ? v0 : log1pf(expf(v0));
    float s = 0.f, mn = 3.0e38f, mx = -3.0e38f;
    int linok = 1;
    if (tid < NK) {
        float v   = phi_log_inc[l * NK + tid];
        float spv = (v > 20.f) ? v : log1pf(expf(v));
        sp[tid] = spv;
        s = spv;
        linok = fabsf(spv - sp0) <= 1e-6f * fabsf(sp0);
        float pc = Phi_coeffs[l * NK + tid];
        mn = pc; mx = pc;
    }
    float tl = 0.f;
    for (int i = tid; i < DD; i += 128) tl += lambdas[l * DD + i];
    #pragma unroll
    for (int off = 16; off > 0; off >>= 1) {
        s  += __shfl_xor_sync(~0u, s,  off);
        tl += __shfl_xor_sync(~0u, tl, off);
        mn  = fminf(mn, __shfl_xor_sync(~0u, mn, off));
        mx  = fmaxf(mx, __shfl_xor_sync(~0u, mx, off));
        linok &= __shfl_xor_sync(~0u, linok, off);
    }
    if (lane == 0) { rS[wid]=s; rL[wid]=tl; rMn[wid]=mn; rMx[wid]=mx; rLin[wid]=linok; }
    __syncthreads();
    const float ss = rS[0]+rS[1]+rS[2]+rS[3];
    const int   L  = rLin[0] & rLin[1] & rLin[2] & rLin[3];
    if (tid == 0) {
        g_lc[l].lin   = L ? 1.f : 0.f;
        g_lc[l].gamma = sp0 / (ss + 1e-8f);
        g_lc[l].Tl    = rL[0]+rL[1]+rL[2]+rL[3];
        g_lc[l].cmin  = fminf(fminf(rMn[0],rMn[1]), fminf(rMn[2],rMn[3]));
        g_lc[l].cmax  = fmaxf(fmaxf(rMx[0],rMx[1]), fmaxf(rMx[2],rMx[3]));
    }
    if (!L) {
        if (tid == 0) {
            float c = 0.f;
            for (int k = 0; k < NK; ++k) { c += sp[k]; cum[k] = c; }
        }
        __syncthreads();
        const float inv = 1.0f / (cum[NK - 1] + 1e-8f);
        const float fix = 99.0f / BETA;
        for (int k = tid; k < NK - 1; k += 128) {
            float c0 = cum[k] * inv;
            float dk = cum[k + 1] * inv - c0;
            g_tab[l][k] = make_float2(dk * fix, fmaf(-(float)k, dk, c0));
        }
    }
}

// One block per batch row; h lives in smem across all 3 layers.
// Paths per layer (linear phi):
//  (a) HISTOGRAM when all h in [0,1) (vote): exact O(D) via threshold bins +
//      (lam, lam*h) prefix scan.  (b) COMPACTION otherwise: dense survivor
//      list, 2-inst/eval.  (c) TABLE fallback for non-linear phi.
__global__ __launch_bounds__(NTHREADS) void sprecher_kernel(
    const float* __restrict__ x,
    const float* __restrict__ lambdas,
    const float* __restrict__ eta,
    const float* __restrict__ Phi_coeffs,
    const float* __restrict__ dc_p, const float* __restrict__ dr_p,
    const float* __restrict__ cc_p, const float* __restrict__ cr_p,
    const float* __restrict__ res_w,
    const float* __restrict__ output_scale,
    float* __restrict__ out)
{
    __shared__ float  h[DD];
    __shared__ __align__(16) float2 phi_tab[99 * 32]; // table / list / hist bins
    __shared__ float4 hl4[DD / 2];
    __shared__ float  Phic[NK];
    __shared__ float  rA[8];
    __shared__ float2 wsum2[8];
    __shared__ int    wcnt[8];

    const int b    = blockIdx.x;
    const int tid  = threadIdx.x;
    const int lane = tid & 31;
    const int wid  = tid >> 5;

    ((float2*)h)[tid] = ((const float2*)(x + b * DD))[tid];

    const float dcv = dc_p[0], drv = dr_p[0], ccv = cc_p[0], crv = cr_p[0];
    const float in_min = dcv - drv, in_max = dcv + drv;
    const float o_min  = ccv - crv, o_max  = ccv + crv;
    const float cap_scale = 99.0f / (in_max - in_min);
    const float2* __restrict__ tabL = (const float2*)phi_tab + lane;

    for (int l = 0; l < NL; ++l) {
        const float etal = eta[l];
        const float rw   = res_w[l];
        const LayerConst lc = g_lc[l];
        const int lin = (lc.lin != 0.f);

        __syncthreads();                                   // B0: h ready, smem reuse safe
        if (tid < NK) Phic[tid] = Phi_coeffs[l * NK + tid];
        const float2 lm = ((const float2*)(lambdas + l * DD))[tid];
        const float2 hp = ((const float2*)h)[tid];
        const float hx = hp.x, hz = hp.y;
        // zero hist bins (only hist path reads them as bins)
        const float2 z2 = make_float2(0.f, 0.f);
        phi_tab[tid] = z2; phi_tab[tid + NTHREADS] = z2;

        const int allin = __syncthreads_and(hx >= 0.f && hx < 1.0f &&
                                            hz >= 0.f && hz < 1.0f);   // B1

        const float co0 = etal * (float)tid;
        const float co1 = etal * (float)(tid + NTHREADS);
        float acc0 = 0.f, acc1 = 0.f;

        if (lin && allin) {
            // ---- HISTOGRAM: thresholds spread, no permanent saturation ----
            float tlh = lm.x * hx + lm.y * hz;
            #pragma unroll
            for (int off = 16; off > 0; off >>= 1)
                tlh += __shfl_xor_sync(~0u, tlh, off);
            if (lane == 0) rA[wid] = tlh;
            const float inv_eta = 1.0f / etal;
            {
                int ou = __float2int_ru((1.0f - hx) * inv_eta);
                ou = max(ou, 0);
                if (ou <= 511) { atomicAdd(&phi_tab[ou].x, lm.x);
                                 atomicAdd(&phi_tab[ou].y, lm.x * hx); }
                int ov = __float2int_ru((1.0f - hz) * inv_eta);
                ov = max(ov, 0);
                if (ov <= 511) { atomicAdd(&phi_tab[ov].x, lm.y);
                                 atomicAdd(&phi_tab[ov].y, lm.y * hz); }
            }
            __syncthreads();                               // B2: hist + partials done
            float Tlh = 0.f;
            #pragma unroll
            for (int w = 0; w < 8; ++w) Tlh += rA[w];
            // inclusive float2 scan over 512 bins (2 bins/thread)
            float4 ac = ((const float4*)phi_tab)[tid];
            float2 s = make_float2(ac.x + ac.z, ac.y + ac.w);
            #pragma unroll
            for (int d = 1; d < 32; d <<= 1) {
                float nx = __shfl_up_sync(~0u, s.x, d);
                float ny = __shfl_up_sync(~0u, s.y, d);
                if (lane >= d) { s.x += nx; s.y += ny; }
            }
            if (lane == 31) wsum2[wid] = s;
            __syncthreads();                               // B3
            float ox = 0.f, oy = 0.f;
            #pragma unroll
            for (int w = 0; w < 8; ++w)
                if (w < wid) { ox += wsum2[w].x; oy += wsum2[w].y; }
            float p1x = ox + s.x, p1y = oy + s.y;
            ((float4*)phi_tab)[tid] = make_float4(p1x - ac.z, p1y - ac.w, p1x, p1y);
            __syncthreads();                               // B4
            const float Tl = lc.Tl;
            const float g99  = 99.0f * lc.gamma;
            const float base = lc.gamma * Tl;
            {
                float2 P = phi_tab[tid];
                acc0 = fmaf(g99, P.x + (Tlh - P.y) + co0 * (Tl - P.x), base);
            }
            {
                float2 P = phi_tab[tid + NTHREADS];
                acc1 = fmaf(g99, P.x + (Tlh - P.y) + co1 * (Tl - P.x), base);
            }
        } else if (lin) {
            // ---- COMPACTION: some elements permanently clamped ----
            float s1 = ((hx >= 1.0f) ? lm.x : 0.f) + ((hz >= 1.0f) ? lm.y : 0.f);
            const float comax = etal * 511.0f;
            const bool a0 = (hx > -comax) && (hx < 1.0f);
            const bool a1 = (hz > -comax) && (hz < 1.0f);
            int c = (int)a0 + (int)a1;
            int incl = c;
            #pragma unroll
            for (int d = 1; d < 32; d <<= 1) {
                int n = __shfl_up_sync(~0u, incl, d);
                if (lane >= d) incl += n;
            }
            #pragma unroll
            for (int off = 16; off > 0; off >>= 1)
                s1 += __shfl_xor_sync(~0u, s1, off);
            if (lane == 31) wcnt[wid] = incl;
            if (lane == 0)  rA[wid] = s1;
            __syncthreads();                               // B2
            int wbase = 0, tot = 0;
            float S1 = 0.f;
            #pragma unroll
            for (int w = 0; w < 8; ++w) {
                if (w < wid) wbase += wcnt[w];
                tot += wcnt[w];
                S1  += rA[w];
            }
            int pos = wbase + incl - c;
            if (a0) phi_tab[pos++] = make_float2(hx, lm.x);
            if (a1) phi_tab[pos]   = make_float2(hz, lm.y);
            if (tid == 0 && (tot & 1)) phi_tab[tot] = make_float2(0.f, 0.f);
            const int n2 = (tot + 1) >> 1;
            __syncthreads();                               // B3
            const float4* __restrict__ lst = (const float4*)phi_tab;
            #pragma unroll 4
            for (int j = 0; j < n2; ++j) {
                const float4 hv = lst[j];
                acc0 = fmaf(hv.y, __saturatef(hv.x + co0), acc0);
                acc1 = fmaf(hv.y, __saturatef(hv.x + co1), acc1);
                acc0 = fmaf(hv.w, __saturatef(hv.z + co0), acc0);
                acc1 = fmaf(hv.w, __saturatef(hv.z + co1), acc1);
            }
            const float g99  = 99.0f * lc.gamma;
            const float base = lc.gamma * lc.Tl;
            acc0 = fmaf(g99, acc0 + S1, base);
            acc1 = fmaf(g99, acc1 + S1, base);
        } else {
            // ---- TABLE fallback (exact piecewise-linear phi) ----
            hl4[tid] = make_float4(hx, lm.x, hz, lm.y);
            for (int idx = tid; idx < 99 * 32; idx += NTHREADS)
                phi_tab[idx] = g_tab[l][idx >> 5];
            __syncthreads();
            #pragma unroll 4
            for (int i2 = 0; i2 < DD / 2; ++i2) {
                const float4 hv = hl4[i2];
                { float u = __saturatef(hv.x + co0) * BETA; float2 t = tabL[((int)u) * 32];
                  acc0 = fmaf(hv.y, fmaf(u, t.x, t.y), acc0); }
                { float u = __saturatef(hv.x + co1) * BETA; float2 t = tabL[((int)u) * 32];
                  acc1 = fmaf(hv.y, fmaf(u, t.x, t.y), acc1); }
                { float u = __saturatef(hv.z + co0) * BETA; float2 t = tabL[((int)u) * 32];
                  acc0 = fmaf(hv.w, fmaf(u, t.x, t.y), acc0); }
                { float u = __saturatef(hv.z + co1) * BETA; float2 t = tabL[((int)u) * 32];
                  acc1 = fmaf(hv.w, fmaf(u, t.x, t.y), acc1); }
            }
        }

        // Epilogue: Phi spline + renorm + residual
        const float cmin = lc.cmin, cmax = lc.cmax;
        const float inv_norm = 1.0f / (cmax - cmin + 1e-8f);
        float act0, act1;
        {
            float s   = acc0 + (float)tid;
            float scv = fminf(fmaxf(s, in_min), in_max);
            float u   = (scv - in_min) * cap_scale;
            int   k   = (int)u; k = min(k, 98);
            float f   = u - (float)k;
            float c0  = Phic[k], c1 = Phic[k + 1];
            float raw = fmaf(f, c1 - c0, c0);
            float rn  = fminf(fmaxf((raw - cmin) * inv_norm, 0.f), 1.f);
            act0 = fmaf(o_max - o_min, rn, o_min) + rw * h[tid];
        }
        {
            float s   = acc1 + (float)(tid + NTHREADS);
            float scv = fminf(fmaxf(s, in_min), in_max);
            float u   = (scv - in_min) * cap_scale;
            int   k   = (int)u; k = min(k, 98);
            float f   = u - (float)k;
            float c0  = Phic[k], c1 = Phic[k + 1];
            float raw = fmaf(f, c1 - c0, c0);
            float rn  = fminf(fmaxf((raw - cmin) * inv_norm, 0.f), 1.f);
            act1 = fmaf(o_max - o_min, rn, o_min) + rw * h[tid + NTHREADS];
        }

        if (l < NL - 1) {
            __syncthreads();
            h[tid]            = act0;
            h[tid + NTHREADS] = act1;
        } else {
            float v = act0 + act1;
            #pragma unroll
            for (int off = 16; off > 0; off >>= 1)
                v += __shfl_xor_sync(0xffffffffu, v, off);
            if (lane == 0) rA[wid] = v;
            __syncthreads();
            if (tid == 0) {
                float r = 0.f;
                #pragma unroll
                for (int w = 0; w < NTHREADS / 32; ++w) r += rA[w];
                out[b] = r * output_scale[0];
            }
        }
    }
}

extern "C" void kernel_launch(void* const* d_in, const int* in_sizes, int n_in,
                              void* d_out, int out_size)
{
    const float* x            = (const float*)d_in[0];
    const float* lambdas      = (const float*)d_in[1];
    const float* eta          = (const float*)d_in[2];
    const float* phi_log_inc  = (const float*)d_in[3];
    const float* Phi_coeffs   = (const float*)d_in[4];
    const float* dc           = (const float*)d_in[5];
    const float* dr           = (const float*)d_in[6];
    const float* cc           = (const float*)d_in[7];
    const float* cr           = (const float*)d_in[8];
    const float* res_w        = (const float*)d_in[9];
    const float* output_scale = (const float*)d_in[10];
    float* out = (float*)d_out;

    setup_kernel<<<NL, 128>>>(lambdas, phi_log_inc, Phi_coeffs);
    sprecher_kernel<<<BD, NTHREADS>>>(x, lambdas, eta, Phi_coeffs,
                                      dc, dr, cc, cr, res_w, output_scale, out);
}

// round 17
// speedup vs baseline: 3.5622x; 1.1318x over previous
#include <cuda_runtime.h>
#include <cuda_bf16.h>

#define BD 512
#define DD 512
#define NL 3
#define NK 100
#define NTHREADS 256
#define BETA 98.999992f

// One block per batch row; h lives in smem across all 3 layers. Single launch.
// Layer-constant work is done in-block but cheaply:
//   lin  <=> all raw phi_log_inc equal (softplus injective -> no softplus)
//   gamma = sp0/(100*sp0+eps)  (one softplus per thread, redundant)
//   Tl/cmin/cmax: one 3-quantity shfl chain
// Paths (linear phi):
//  (a) HISTOGRAM when all h in [0,1): exact O(D) via threshold bins +
//      (lam, lam*h) prefix scan.  (b) COMPACTION otherwise: dense survivor
//      list, 2-inst/eval.  (c) TABLE fallback for non-linear phi (in-block).
__global__ __launch_bounds__(NTHREADS) void sprecher_kernel(
    const float* __restrict__ x,
    const float* __restrict__ lambdas,
    const float* __restrict__ eta,
    const float* __restrict__ phi_log_inc,
    const float* __restrict__ Phi_coeffs,
    const float* __restrict__ dc_p, const float* __restrict__ dr_p,
    const float* __restrict__ cc_p, const float* __restrict__ cr_p,
    const float* __restrict__ res_w,
    const float* __restrict__ output_scale,
    float* __restrict__ out)
{
    __shared__ float  h[DD];
    __shared__ __align__(16) float2 phi_tab[99 * 32]; // table / list / hist bins
    __shared__ float4 hl4[DD / 2];
    __shared__ float  Phic[NK];
    __shared__ float  coef[NK];                       // fallback only
    __shared__ float  s_inv;                          // fallback only
    __shared__ float  rA[8], rT[8], rMn[8], rMx[8];
    __shared__ float2 wsum2[8];
    __shared__ int    wcnt[8];

    const int b    = blockIdx.x;
    const int tid  = threadIdx.x;
    const int lane = tid & 31;
    const int wid  = tid >> 5;

    ((float2*)h)[tid] = ((const float2*)(x + b * DD))[tid];

    const float dcv = dc_p[0], drv = dr_p[0], ccv = cc_p[0], crv = cr_p[0];
    const float in_min = dcv - drv, in_max = dcv + drv;
    const float o_min  = ccv - crv, o_max  = ccv + crv;
    const float cap_scale = 99.0f / (in_max - in_min);
    const float2* __restrict__ tabL = (const float2*)phi_tab + lane;

    for (int l = 0; l < NL; ++l) {
        const float etal = eta[l];
        const float rw   = res_w[l];

        __syncthreads();                                   // B0: h ready, smem reuse safe

        float pc = 0.f, v = 0.f;
        if (tid < NK) {
            pc = Phi_coeffs[l * NK + tid];
            Phic[tid] = pc;
            v = phi_log_inc[l * NK + tid];
        }
        const float v0 = phi_log_inc[l * NK];              // uniform
        const bool linok = (tid >= NK) ||
                           (fabsf(v - v0) <= 1e-6f * fabsf(v0));

        const float2 lm = ((const float2*)(lambdas + l * DD))[tid];
        const float2 hp = ((const float2*)h)[tid];
        const float hx = hp.x, hz = hp.y;

        // 3-quantity chain: Tl, Phic min/max
        float tl = lm.x + lm.y;
        float mn = (tid < NK) ? pc : 3.0e38f;
        float mx = (tid < NK) ? pc : -3.0e38f;
        #pragma unroll
        for (int off = 16; off > 0; off >>= 1) {
            tl += __shfl_xor_sync(~0u, tl, off);
            mn  = fminf(mn, __shfl_xor_sync(~0u, mn, off));
            mx  = fmaxf(mx, __shfl_xor_sync(~0u, mx, off));
        }
        if (lane == 0) { rT[wid] = tl; rMn[wid] = mn; rMx[wid] = mx; }

        // zero hist bins (only hist path reads them as bins)
        const float2 z2 = make_float2(0.f, 0.f);
        phi_tab[tid] = z2; phi_tab[tid + NTHREADS] = z2;

        const bool in01 = (hx >= 0.f) && (hx < 1.0f) && (hz >= 0.f) && (hz < 1.0f);
        const int fast = __syncthreads_and(linok && in01); // B1 (also publishes rT/rMn/rMx)
        int lin = fast;
        if (!fast) lin = __syncthreads_and(linok);         // B1b (uniform branch)

        float Tl = 0.f, cmin = 3.0e38f, cmax = -3.0e38f;
        #pragma unroll
        for (int w = 0; w < 8; ++w) {
            Tl += rT[w];
            cmin = fminf(cmin, rMn[w]);
            cmax = fmaxf(cmax, rMx[w]);
        }
        const float sp0   = (v0 > 20.f) ? v0 : log1pf(expf(v0));
        const float gamma = sp0 / (100.0f * sp0 + 1e-8f);

        const float co0 = etal * (float)tid;
        const float co1 = etal * (float)(tid + NTHREADS);
        float acc0 = 0.f, acc1 = 0.f;

        if (fast) {
            // ---- HISTOGRAM: all h in [0,1), thresholds spread ----
            float tlh = lm.x * hx + lm.y * hz;
            #pragma unroll
            for (int off = 16; off > 0; off >>= 1)
                tlh += __shfl_xor_sync(~0u, tlh, off);
            if (lane == 0) rA[wid] = tlh;
            const float inv_eta = 1.0f / etal;
            {
                int ou = __float2int_ru((1.0f - hx) * inv_eta);
                ou = max(ou, 0);
                if (ou <= 511) { atomicAdd(&phi_tab[ou].x, lm.x);
                                 atomicAdd(&phi_tab[ou].y, lm.x * hx); }
                int ov = __float2int_ru((1.0f - hz) * inv_eta);
                ov = max(ov, 0);
                if (ov <= 511) { atomicAdd(&phi_tab[ov].x, lm.y);
                                 atomicAdd(&phi_tab[ov].y, lm.y * hz); }
            }
            __syncthreads();                               // B2: hist + partials done
            float Tlh = 0.f;
            #pragma unroll
            for (int w = 0; w < 8; ++w) Tlh += rA[w];
            // inclusive float2 scan over 512 bins (2 bins/thread)
            float4 ac = ((const float4*)phi_tab)[tid];
            float2 s = make_float2(ac.x + ac.z, ac.y + ac.w);
            #pragma unroll
            for (int d = 1; d < 32; d <<= 1) {
                float nx = __shfl_up_sync(~0u, s.x, d);
                float ny = __shfl_up_sync(~0u, s.y, d);
                if (lane >= d) { s.x += nx; s.y += ny; }
            }
            if (lane == 31) wsum2[wid] = s;
            __syncthreads();                               // B3
            float ox = 0.f, oy = 0.f;
            #pragma unroll
            for (int w = 0; w < 8; ++w)
                if (w < wid) { ox += wsum2[w].x; oy += wsum2[w].y; }
            float p1x = ox + s.x, p1y = oy + s.y;
            ((float4*)phi_tab)[tid] = make_float4(p1x - ac.z, p1y - ac.w, p1x, p1y);
            __syncthreads();                               // B4
            const float g99  = 99.0f * gamma;
            const float base = gamma * Tl;
            {
                float2 P = phi_tab[tid];
                acc0 = fmaf(g99, P.x + (Tlh - P.y) + co0 * (Tl - P.x), base);
            }
            {
                float2 P = phi_tab[tid + NTHREADS];
                acc1 = fmaf(g99, P.x + (Tlh - P.y) + co1 * (Tl - P.x), base);
            }
        } else if (lin) {
            // ---- COMPACTION: some elements permanently clamped ----
            float s1 = ((hx >= 1.0f) ? lm.x : 0.f) + ((hz >= 1.0f) ? lm.y : 0.f);
            const float comax = etal * 511.0f;
            const bool a0 = (hx > -comax) && (hx < 1.0f);
            const bool a1 = (hz > -comax) && (hz < 1.0f);
            int c = (int)a0 + (int)a1;
            int incl = c;
            #pragma unroll
            for (int d = 1; d < 32; d <<= 1) {
                int n = __shfl_up_sync(~0u, incl, d);
                if (lane >= d) incl += n;
            }
            #pragma unroll
            for (int off = 16; off > 0; off >>= 1)
                s1 += __shfl_xor_sync(~0u, s1, off);
            if (lane == 31) wcnt[wid] = incl;
            if (lane == 0)  rA[wid] = s1;
            __syncthreads();                               // B2
            int wbase = 0, tot = 0;
            float S1 = 0.f;
            #pragma unroll
            for (int w = 0; w < 8; ++w) {
                if (w < wid) wbase += wcnt[w];
                tot += wcnt[w];
                S1  += rA[w];
            }
            int pos = wbase + incl - c;
            if (a0) phi_tab[pos++] = make_float2(hx, lm.x);
            if (a1) phi_tab[pos]   = make_float2(hz, lm.y);
            if (tid == 0 && (tot & 1)) phi_tab[tot] = make_float2(0.f, 0.f);
            const int n2 = (tot + 1) >> 1;
            __syncthreads();                               // B3
            const float4* __restrict__ lst = (const float4*)phi_tab;
            #pragma unroll 4
            for (int j = 0; j < n2; ++j) {
                const float4 hv = lst[j];
                acc0 = fmaf(hv.y, __saturatef(hv.x + co0), acc0);
                acc1 = fmaf(hv.y, __saturatef(hv.x + co1), acc1);
                acc0 = fmaf(hv.w, __saturatef(hv.z + co0), acc0);
                acc1 = fmaf(hv.w, __saturatef(hv.z + co1), acc1);
            }
            const float g99  = 99.0f * gamma;
            const float base = gamma * Tl;
            acc0 = fmaf(g99, acc0 + S1, base);
            acc1 = fmaf(g99, acc1 + S1, base);
        } else {
            // ---- TABLE fallback (exact piecewise-linear phi), in-block ----
            if (tid < NK) {
                float spv = (v > 20.f) ? v : log1pf(expf(v));
                coef[tid] = spv;
            }
            hl4[tid] = make_float4(hx, lm.x, hz, lm.y);
            __syncthreads();
            if (tid == 0) {
                float cum = 0.f;
                for (int k = 0; k < NK; ++k) { cum += coef[k]; coef[k] = cum; }
                s_inv = 1.0f / (cum + 1e-8f);
            }
            __syncthreads();
            {
                const float inv = s_inv;
                const float fix = 99.0f / BETA;
                for (int idx = tid; idx < 99 * 32; idx += NTHREADS) {
                    int k = idx >> 5;
                    float c0 = coef[k] * inv;
                    float dk = coef[k + 1] * inv - c0;
                    phi_tab[idx] = make_float2(dk * fix, fmaf(-(float)k, dk, c0));
                }
            }
            __syncthreads();
            #pragma unroll 4
            for (int i2 = 0; i2 < DD / 2; ++i2) {
                const float4 hv = hl4[i2];
                { float u = __saturatef(hv.x + co0) * BETA; float2 t = tabL[((int)u) * 32];
                  acc0 = fmaf(hv.y, fmaf(u, t.x, t.y), acc0); }
                { float u = __saturatef(hv.x + co1) * BETA; float2 t = tabL[((int)u) * 32];
                  acc1 = fmaf(hv.y, fmaf(u, t.x, t.y), acc1); }
                { float u = __saturatef(hv.z + co0) * BETA; float2 t = tabL[((int)u) * 32];
                  acc0 = fmaf(hv.w, fmaf(u, t.x, t.y), acc0); }
                { float u = __saturatef(hv.z + co1) * BETA; float2 t = tabL[((int)u) * 32];
                  acc1 = fmaf(hv.w, fmaf(u, t.x, t.y), acc1); }
            }
        }

        // Epilogue: Phi spline + renorm + residual
        const float inv_norm = 1.0f / (cmax - cmin + 1e-8f);
        float act0, act1;
        {
            float s   = acc0 + (float)tid;
            float scv = fminf(fmaxf(s, in_min), in_max);
            float u   = (scv - in_min) * cap_scale;
            int   k   = (int)u; k = min(k, 98);
            float f   = u - (float)k;
            float c0  = Phic[k], c1 = Phic[k + 1];
            float raw = fmaf(f, c1 - c0, c0);
            float rn  = fminf(fmaxf((raw - cmin) * inv_norm, 0.f), 1.f);
            act0 = fmaf(o_max - o_min, rn, o_min) + rw * h[tid];
        }
        {
            float s   = acc1 + (float)(tid + NTHREADS);
            float scv = fminf(fmaxf(s, in_min), in_max);
            float u   = (scv - in_min) * cap_scale;
            int   k   = (int)u; k = min(k, 98);
            float f   = u - (float)k;
            float c0  = Phic[k], c1 = Phic[k + 1];
            float raw = fmaf(f, c1 - c0, c0);
            float rn  = fminf(fmaxf((raw - cmin) * inv_norm, 0.f), 1.f);
            act1 = fmaf(o_max - o_min, rn, o_min) + rw * h[tid + NTHREADS];
        }

        if (l < NL - 1) {
            __syncthreads();
            h[tid]            = act0;
            h[tid + NTHREADS] = act1;
        } else {
            float vsum = act0 + act1;
            #pragma unroll
            for (int off = 16; off > 0; off >>= 1)
                vsum += __shfl_xor_sync(0xffffffffu, vsum, off);
            if (lane == 0) rA[wid] = vsum;
            __syncthreads();
            if (tid == 0) {
                float r = 0.f;
                #pragma unroll
                for (int w = 0; w < NTHREADS / 32; ++w) r += rA[w];
                out[b] = r * output_scale[0];
            }
        }
    }
}

extern "C" void kernel_launch(void* const* d_in, const int* in_sizes, int n_in,
                              void* d_out, int out_size)
{
    const float* x            = (const float*)d_in[0];
    const float* lambdas      = (const float*)d_in[1];
    const float* eta          = (const float*)d_in[2];
    const float* phi_log_inc  = (const float*)d_in[3];
    const float* Phi_coeffs   = (const float*)d_in[4];
    const float* dc           = (const float*)d_in[5];
    const float* dr           = (const float*)d_in[6];
    const float* cc           = (const float*)d_in[7];
    const float* cr           = (const float*)d_in[8];
    const float* res_w        = (const float*)d_in[9];
    const float* output_scale = (const float*)d_in[10];
    float* out = (float*)d_out;

    sprecher_kernel<<<BD, NTHREADS>>>(x, lambdas, eta, phi_log_inc, Phi_coeffs,
                                      dc, dr, cc, cr, res_w, output_scale, out);
}